// round 14
// baseline (speedup 1.0000x reference)
#include <cuda_runtime.h>
#include <cuda_fp16.h>

// Trilinear 3D grid sample, (y,z,c)-fused fp16 corner layout.
// im:      [B, X, Y, Z, C] float32, B=2, X=Y=Z=160, C=2
// defgrid: [B, X, Y, Z, 3] float32
// out:     [B, X, Y, Z, C] float32
//
// P2[x][y][z] = 8 halves (16B): {(y,z),(y,z+1),(y+1,z),(y+1,z+1)} x {c0,c1}.
// One shared table, sequential per-batch phases.
// Streaming uses HARD cache-bypass semantics so the table stays L2-resident:
//   defgrid: ld.global.cv (not retained), out: st.global.wt (write-through),
//   im: .cs (keeps y-row reuse in preprocess). Table: normal __ldg.

#define XD 160
#define YD 160
#define ZD 160
#define BD 2
#define VOL (XD * YD * ZD)          // 4,096,000
#define THREADS 256
#define PRE_BLOCKS (VOL / 2 / THREADS)      // 8000 (2 voxels/thread)
#define GATHER_BLOCKS (VOL / 2 / THREADS)   // 8000 (2 voxels/thread)

__device__ uint4 g_P2[VOL];   // single shared table (rebuilt per batch)

__device__ __forceinline__ unsigned int pack_h2(float a, float b) {
    __half2 h = __floats2half2_rn(a, b);
    return *(unsigned int*)&h;
}

// ---------- preprocess: 2 consecutive-z voxels per thread ----------
__global__ __launch_bounds__(THREADS) void preprocess_kernel(
    const float2* __restrict__ im, int b)
{
    int t = blockIdx.x * THREADS + threadIdx.x;
    if (t >= VOL / 2) return;

    int i = t * 2;              // even; ZD=160 even => pair stays in one z-row
    int z = i % ZD;             // even, 0..158
    int y = (i / ZD) % YD;

    const float2* __restrict__ imb = im + (size_t)b * VOL;
    int yp = (y < YD - 1) ? ZD : 0;   // clamp y+1
    int j  = i + yp;

    float4 a4 = __ldcs((const float4*)(imb + i));
    float2 c  = (z + 2 < ZD) ? __ldcs(&imb[i + 2]) : make_float2(a4.z, a4.w);
    float4 b4 = __ldcs((const float4*)(imb + j));
    float2 d  = (z + 2 < ZD) ? __ldcs(&imb[j + 2]) : make_float2(b4.z, b4.w);

    uint4 p0, p1;
    p0.x = pack_h2(a4.x, a4.y);   // (y  , z  )
    p0.y = pack_h2(a4.z, a4.w);   // (y  , z+1)
    p0.z = pack_h2(b4.x, b4.y);   // (y+1, z  )
    p0.w = pack_h2(b4.z, b4.w);   // (y+1, z+1)

    p1.x = p0.y;                  // (y  , z+1)
    p1.y = pack_h2(c.x, c.y);     // (y  , z+2 clamped)
    p1.z = p0.w;                  // (y+1, z+1)
    p1.w = pack_h2(d.x, d.y);     // (y+1, z+2 clamped)

    g_P2[i]     = p0;
    g_P2[i + 1] = p1;
}

__device__ __forceinline__ float2 h2f(unsigned int u) {
    __half2 h = *(__half2*)&u;
    return __half22float2(h);
}

__device__ __forceinline__ float2 interp_voxel(
    float x, float y, float z, uint4 q0, uint4 q1,
    int x0, int y0u, int z0u, int zc)
{
    // Lower-edge clip duplication (coords >= 0 so ~never taken; keeps exact
    // reference semantics).
    if (z0u < 0) { q0.y = q0.x; q0.w = q0.z; q1.y = q1.x; q1.w = q1.z; }
    if (y0u < 0) { q0.z = q0.x; q0.w = q0.y; q1.z = q1.x; q1.w = q1.y; }

    float2 Ia = h2f(q0.x), Ib = h2f(q0.y), Ic = h2f(q0.z), Id = h2f(q0.w);
    float2 Ie = h2f(q1.x), If = h2f(q1.y), Ig = h2f(q1.z), Ih = h2f(q1.w);

    int y0 = min(max(y0u, 0), YD - 1);
    const float xd = x - (float)x0;
    const float yd = y - (float)y0;
    const float zd = z - (float)zc;
    const float xm = 1.0f - xd;
    const float ym = 1.0f - yd;
    const float zm = 1.0f - zd;

    float cae0 = Ia.x * xm + Ie.x * xd;
    float cae1 = Ia.y * xm + Ie.y * xd;
    float cbf0 = Ib.x * xm + If.x * xd;
    float cbf1 = Ib.y * xm + If.y * xd;
    float ccg0 = Ic.x * xm + Ig.x * xd;
    float ccg1 = Ic.y * xm + Ig.y * xd;
    float cdh0 = Id.x * xm + Ih.x * xd;
    float cdh1 = Id.y * xm + Ih.y * xd;

    float c0_0 = cae0 * ym + ccg0 * yd;
    float c0_1 = cae1 * ym + ccg1 * yd;
    float c1_0 = cbf0 * ym + cdh0 * yd;
    float c1_1 = cbf1 * ym + cdh1 * yd;

    float2 r;
    r.x = c0_0 * zm + c1_0 * zd;
    r.y = c0_1 * zm + c1_1 * zd;
    return r;
}

// ---------- gather: one voxel-pair per thread ----------
__global__ __launch_bounds__(THREADS) void gather_kernel(
    const float* __restrict__ defgrid,
    float4* __restrict__ out, int b)
{
    int t = blockIdx.x * THREADS + threadIdx.x;
    if (t >= VOL / 2) return;

    int i  = t * 2;
    int gi = b * VOL + i;

    // coords: 3 coalesced float2 loads, volatile-cache (no L2 retention)
    const float2* dg = (const float2*)(defgrid + (size_t)3 * gi);
    float2 d0 = __ldcv(dg + 0);   // xA, yA
    float2 d1 = __ldcv(dg + 1);   // zA, xB
    float2 d2 = __ldcv(dg + 2);   // yB, zB

    const float xA = d0.x, yA = d0.y, zA = d1.x;
    const float xB = d1.y, yB = d2.x, zB = d2.y;

    int xA0u = (int)floorf(xA), yA0u = (int)floorf(yA), zA0u = (int)floorf(zA);
    int xA0 = min(max(xA0u, 0), XD - 1);
    int xA1 = min(max(xA0u + 1, 0), XD - 1);
    int yA0 = min(max(yA0u, 0), YD - 1);
    int zAc = min(max(zA0u, 0), ZD - 1);

    int xB0u = (int)floorf(xB), yB0u = (int)floorf(yB), zB0u = (int)floorf(zB);
    int xB0 = min(max(xB0u, 0), XD - 1);
    int xB1 = min(max(xB0u + 1, 0), XD - 1);
    int yB0 = min(max(yB0u, 0), YD - 1);
    int zBc = min(max(zB0u, 0), ZD - 1);

    uint4 qA0 = __ldg(&g_P2[(xA0 * YD + yA0) * ZD + zAc]);
    uint4 qA1 = __ldg(&g_P2[(xA1 * YD + yA0) * ZD + zAc]);
    uint4 qB0 = __ldg(&g_P2[(xB0 * YD + yB0) * ZD + zBc]);
    uint4 qB1 = __ldg(&g_P2[(xB1 * YD + yB0) * ZD + zBc]);

    float2 rA = interp_voxel(xA, yA, zA, qA0, qA1, xA0, yA0u, zA0u, zAc);
    float2 rB = interp_voxel(xB, yB, zB, qB0, qB1, xB0, yB0u, zB0u, zBc);

    // write-through store: no L2 allocation for output
    __stwt(&out[gi / 2], make_float4(rA.x, rA.y, rB.x, rB.y));
}

extern "C" void kernel_launch(void* const* d_in, const int* in_sizes, int n_in,
                              void* d_out, int out_size)
{
    const float2* im     = (const float2*)d_in[0];
    const float* defgrid = (const float*)d_in[1];
    float4* out          = (float4*)d_out;

    for (int b = 0; b < BD; b++) {
        preprocess_kernel<<<PRE_BLOCKS, THREADS>>>(im, b);
        gather_kernel<<<GATHER_BLOCKS, THREADS>>>(defgrid, out, b);
    }
}